// round 1
// baseline (speedup 1.0000x reference)
#include <cuda_runtime.h>
#include <math.h>

// Problem constants
#define BATCH   64
#define T_LEN   262144
#define STEP    171
#define NSEG    1531          // (262144-512)/171 + 1
#define NPAIR   766           // ceil(NSEG/2); last pair has only the real half
#define NFFT    512
#define FS_F    3152.0f

// Scratch (no allocations allowed)
__device__ float g_partial[BATCH * NPAIR];
__device__ float g_level[BATCH];

__device__ __forceinline__ int brev9(int v) { return (int)(__brev((unsigned)v) >> 23); }

__device__ __forceinline__ float aweight(int k) {
    // 10**(A(f)/10) = (num/den)^2 * 10^0.2   (A1000 = -2 folded in)
    float f   = k * (FS_F / 512.0f);          // k * 6.15625
    float fsq = f * f;
    float num = (12194.0f * 12194.0f) * fsq * fsq;
    float den = (fsq + 20.6f * 20.6f)
              * sqrtf((fsq + 107.7f * 107.7f) * (fsq + 737.9f * 737.9f))
              * (fsq + 12194.0f * 12194.0f);
    float r = num / den;
    return r * r * 1.5848931924611136f;       // 10^0.2
}

// One block = one PAIR of segments (packed real+imag), 128 threads.
// Radix-2 DIF FFT-512 in shared memory, bit-reversed output.
// acc = sum_{k=1..243} aw_k * (|Z_k|^2 + |Z_{512-k}|^2)
//     = sum_k aw_k * 2*(|A_k|^2 + |B_k|^2)   (one-sided x2 folded in)
__global__ __launch_bounds__(128) void fft_pair_kernel(const float* __restrict__ x)
{
    __shared__ float sre[512], sim[512];
    __shared__ float twr[256], twi[256];
    __shared__ float red[4];

    const int t = threadIdx.x;        // 0..127
    const int j = blockIdx.x;         // pair index 0..765
    const int b = blockIdx.y;         // batch

    // Twiddle table: tw[i] = exp(-2*pi*i*I/512), i in [0,256)
    for (int i = t; i < 256; i += 128) {
        float s, c;
        __sincosf(-6.283185307179586f * (float)i * (1.0f / 512.0f), &s, &c);
        twr[i] = c; twi[i] = s;
    }

    const float* xa = x + (size_t)b * T_LEN + (size_t)j * (2 * STEP);
    const bool has_b = (2 * j + 1) < NSEG;

    for (int i = t; i < 512; i += 128) {
        float w = 0.54f - 0.46f * __cosf((float)i * (6.283185307179586f / 512.0f));
        sre[i] = xa[i] * w;
        sim[i] = has_b ? xa[i + STEP] * w : 0.0f;
    }
    __syncthreads();

    // 9 radix-2 DIF stages, half = 256 .. 1
    #pragma unroll
    for (int st = 8; st >= 0; --st) {
        const int half  = 1 << st;
        const int shift = 8 - st;
        #pragma unroll
        for (int u = 0; u < 2; ++u) {
            int bt  = t + u * 128;                       // 0..255
            int pos = bt & (half - 1);
            int i0  = ((bt >> st) << (st + 1)) + pos;
            int i1  = i0 + half;
            float ar = sre[i0], ai = sim[i0];
            float br = sre[i1], bi = sim[i1];
            float dr = ar - br, di = ai - bi;
            float c = twr[pos << shift], s = twi[pos << shift];
            sre[i0] = ar + br;
            sim[i0] = ai + bi;
            sre[i1] = dr * c - di * s;
            sim[i1] = dr * s + di * c;
        }
        __syncthreads();
    }

    // Weighted band power over bins 1..243 (outputs are bit-reversed)
    float acc = 0.0f;
    for (int k = 1 + t; k < 244; k += 128) {
        int ia = brev9(k);
        int ib = brev9(512 - k);
        float p = sre[ia] * sre[ia] + sim[ia] * sim[ia]
                + sre[ib] * sre[ib] + sim[ib] * sim[ib];
        acc += aweight(k) * p;
    }

    // Block reduce (deterministic tree)
    #pragma unroll
    for (int o = 16; o > 0; o >>= 1) acc += __shfl_down_sync(0xffffffffu, acc, o);
    if ((t & 31) == 0) red[t >> 5] = acc;
    __syncthreads();
    if (t == 0)
        g_partial[b * NPAIR + j] = (red[0] + red[1]) + (red[2] + red[3]);
}

// Per-batch reduction -> 10*log10(band * cnorm)
__global__ __launch_bounds__(256) void batch_reduce_kernel(float cnorm)
{
    __shared__ float red[8];
    const int b = blockIdx.x;
    const int t = threadIdx.x;
    float s = 0.0f;
    for (int i = t; i < NPAIR; i += 256) s += g_partial[b * NPAIR + i];
    #pragma unroll
    for (int o = 16; o > 0; o >>= 1) s += __shfl_down_sync(0xffffffffu, s, o);
    if ((t & 31) == 0) red[t >> 5] = s;
    __syncthreads();
    if (t == 0) {
        float band = 0.0f;
        #pragma unroll
        for (int w = 0; w < 8; ++w) band += red[w];
        g_level[b] = 10.0f * log10f(band * cnorm);
    }
}

__global__ void final_kernel(float* __restrict__ out)
{
    __shared__ float red[2];
    const int t = threadIdx.x;   // 64 threads
    float v = g_level[t];
    #pragma unroll
    for (int o = 16; o > 0; o >>= 1) v += __shfl_down_sync(0xffffffffu, v, o);
    if ((t & 31) == 0) red[t >> 5] = v;
    __syncthreads();
    if (t == 0) out[0] = (red[0] + red[1]) * (1.0f / (float)BATCH);
}

extern "C" void kernel_launch(void* const* d_in, const int* in_sizes, int n_in,
                              void* d_out, int out_size)
{
    const float* x = (const float*)d_in[0];
    float* out = (float*)d_out;

    // win_power in double on host (baked into graph; deterministic)
    double wp = 0.0;
    for (int i = 0; i < 512; ++i) {
        double w = 0.54 - 0.46 * cos(2.0 * M_PI * (double)i / 512.0);
        // match fp32 reference window
        float wf = (float)w;
        wp += (double)wf * (double)wf;
    }
    float cnorm = (float)(1.0 / (wp * 3152.0 * (double)NSEG));

    dim3 grid(NPAIR, BATCH);
    fft_pair_kernel<<<grid, 128>>>(x);
    batch_reduce_kernel<<<BATCH, 256>>>(cnorm);
    final_kernel<<<1, 64>>>(out);
}

// round 2
// speedup vs baseline: 3.8361x; 3.8361x over previous
#include <cuda_runtime.h>
#include <math.h>

#define BATCH   64
#define T_LEN   262144
#define STEP    171
#define NSEG    1531
#define NPAIR   766
#define FS_F    3152.0f

// Scratch / tables (no allocations allowed)
__device__ float g_partial[BATCH * NPAIR];
__device__ float g_level[BATCH];
__device__ float g_twr[512], g_twi[512];   // W512^i = exp(-2*pi*i*I/512)
__device__ float g_win[512];               // periodic Hamming
__device__ float g_wp[512];                // folded A-weight per full-spectrum bin

__device__ __forceinline__ float aweight(int k) {
    // 10**(A(f)/10) = (num/den)^2 * 10^0.2   (A1000 = -2 folded in)
    float f   = k * (FS_F / 512.0f);
    float fsq = f * f;
    float num = (12194.0f * 12194.0f) * fsq * fsq;
    float den = (fsq + 20.6f * 20.6f)
              * sqrtf((fsq + 107.7f * 107.7f) * (fsq + 737.9f * 737.9f))
              * (fsq + 12194.0f * 12194.0f);
    float r = num / den;
    return r * r * 1.5848931924611136f;
}

__global__ void init_tables()
{
    int i = threadIdx.x;             // 512 threads
    double ang = -2.0 * M_PI * (double)i / 512.0;
    g_twr[i] = (float)cos(ang);
    g_twi[i] = (float)sin(ang);
    g_win[i] = (float)(0.54 - 0.46 * cos(2.0 * M_PI * (double)i / 512.0));
    int kp = (i < 256) ? i : (512 - i);
    g_wp[i] = (kp >= 1 && kp <= 243) ? aweight(kp) : 0.0f;
}

// In-place DFT-8 (natural order in/out): u_q = sum_p a_p * exp(-2pi i p q / 8)
__device__ __forceinline__ void dft8(float* xr, float* xi)
{
    const float C = 0.70710678118654752f;
    float e0r=xr[0]+xr[4], e0i=xi[0]+xi[4];
    float o0r=xr[0]-xr[4], o0i=xi[0]-xi[4];
    float e1r=xr[1]+xr[5], e1i=xi[1]+xi[5];
    float o1r=xr[1]-xr[5], o1i=xi[1]-xi[5];
    float e2r=xr[2]+xr[6], e2i=xi[2]+xi[6];
    float o2r=xr[2]-xr[6], o2i=xi[2]-xi[6];
    float e3r=xr[3]+xr[7], e3i=xi[3]+xi[7];
    float o3r=xr[3]-xr[7], o3i=xi[3]-xi[7];
    // o1 *= w8^1 = C(1-i); o2 *= -i; o3 *= w8^3 = -C(1+i)
    float t1r = C*(o1r + o1i), t1i = C*(o1i - o1r);
    float t2r = o2i,           t2i = -o2r;
    float t3r = C*(o3i - o3r), t3i = -C*(o3r + o3i);
    // DFT4(e) -> u0,u2,u4,u6
    float a0r=e0r+e2r, a0i=e0i+e2i;
    float a1r=e0r-e2r, a1i=e0i-e2i;
    float a2r=e1r+e3r, a2i=e1i+e3i;
    float a3r=e1r-e3r, a3i=e1i-e3i;
    xr[0]=a0r+a2r; xi[0]=a0i+a2i;
    xr[4]=a0r-a2r; xi[4]=a0i-a2i;
    xr[2]=a1r+a3i; xi[2]=a1i-a3r;
    xr[6]=a1r-a3i; xi[6]=a1i+a3r;
    // DFT4(o with twiddles) -> u1,u3,u5,u7
    float b0r=o0r+t2r, b0i=o0i+t2i;
    float b1r=o0r-t2r, b1i=o0i-t2i;
    float b2r=t1r+t3r, b2i=t1i+t3i;
    float b3r=t1r-t3r, b3i=t1i-t3i;
    xr[1]=b0r+b2r; xi[1]=b0i+b2i;
    xr[5]=b0r-b2r; xi[5]=b0i-b2i;
    xr[3]=b1r+b3i; xi[3]=b1i-b3r;
    xr[7]=b1r-b3i; xi[7]=b1i+b3r;
}

// 8x8 transpose across lanes (lane low-3 bits <-> register index) via shfl_xor
__device__ __forceinline__ void transpose8(float* r, int lane3)
{
    #pragma unroll
    for (int st = 0; st < 3; ++st) {
        const int mask = 1 << st;
        bool up = (lane3 & mask) != 0;
        #pragma unroll
        for (int i = 0; i < 8; ++i) {
            if (!(i & mask)) {
                int j = i | mask;
                float lo = r[i], hi = r[j];
                float send = up ? lo : hi;
                float recv = __shfl_xor_sync(0xffffffffu, send, mask);
                if (up) lo = recv; else hi = recv;
                r[i] = lo; r[j] = hi;
            }
        }
    }
}

// One 128-thread block = 2 packed-pair FFT-512s (64 threads each, 8 pts/thread).
__global__ __launch_bounds__(128) void fft_pair_kernel(const float* __restrict__ x)
{
    __shared__ float exr[2][8][72], exi[2][8][72];
    __shared__ float red[2][2];

    const int g = threadIdx.x >> 6;      // sub-group: which FFT
    const int t = threadIdx.x & 63;      // 0..63 within FFT
    const int j = blockIdx.x * 2 + g;    // pair index 0..765
    const int b = blockIdx.y;

    const float* xa = x + (size_t)b * T_LEN + (size_t)j * (2 * STEP);
    const bool has_b = (2 * j + 1) < NSEG;

    float vr[8], vi[8];

    // Load 8 strided points, window, pack pair (A=real, B=imag)
    #pragma unroll
    for (int p = 0; p < 8; ++p) {
        int i = t + (p << 6);
        float w = g_win[i];
        vr[p] = xa[i] * w;
        vi[p] = has_b ? xa[i + STEP] * w : 0.0f;
    }

    // Pass 1: DFT-8 over p, twiddle W512^{t*q}
    dft8(vr, vi);
    #pragma unroll
    for (int q = 1; q < 8; ++q) {
        float c = g_twr[t * q], s = g_twi[t * q];
        float rr = vr[q], ii = vi[q];
        vr[q] = rr * c - ii * s;
        vi[q] = rr * s + ii * c;
    }

    // Exchange 1 (padded stride 72 -> conflict-free both directions)
    #pragma unroll
    for (int q = 0; q < 8; ++q) { exr[g][q][t] = vr[q]; exi[g][q][t] = vi[q]; }
    __syncthreads();
    const int qp = t >> 3, m = t & 7;
    #pragma unroll
    for (int s = 0; s < 8; ++s) {
        vr[s] = exr[g][qp][m + (s << 3)];
        vi[s] = exi[g][qp][m + (s << 3)];
    }

    // Pass 2: DFT-8 over s, twiddle W64^{m*q2} = W512^{8*m*q2}
    dft8(vr, vi);
    #pragma unroll
    for (int q2 = 1; q2 < 8; ++q2) {
        int idx = (m * q2) << 3;
        float c = g_twr[idx], s = g_twi[idx];
        float rr = vr[q2], ii = vi[q2];
        vr[q2] = rr * c - ii * s;
        vi[q2] = rr * s + ii * c;
    }

    // Transpose (lane m <-> register q2) in-warp, then pass 3: DFT-8 over m
    transpose8(vr, m);
    transpose8(vi, m);
    dft8(vr, vi);

    // Thread now owns bins k = 64*r2 + 8*(t&7) + qp for r2=0..7.
    // Weighted power with folded one-sided A-weight table.
    const int base = (m << 3) + qp;
    float acc = 0.0f;
    #pragma unroll
    for (int r2 = 0; r2 < 8; ++r2) {
        int k = (r2 << 6) + base;
        acc += g_wp[k] * (vr[r2] * vr[r2] + vi[r2] * vi[r2]);
    }

    // Reduce 64 threads of this sub-group (deterministic tree)
    #pragma unroll
    for (int o = 16; o > 0; o >>= 1) acc += __shfl_down_sync(0xffffffffu, acc, o);
    if ((t & 31) == 0) red[g][t >> 5] = acc;
    __syncthreads();
    if (t == 0) g_partial[b * NPAIR + j] = red[g][0] + red[g][1];
}

__global__ __launch_bounds__(256) void batch_reduce_kernel(float cnorm)
{
    __shared__ float red[8];
    const int b = blockIdx.x;
    const int t = threadIdx.x;
    float s = 0.0f;
    for (int i = t; i < NPAIR; i += 256) s += g_partial[b * NPAIR + i];
    #pragma unroll
    for (int o = 16; o > 0; o >>= 1) s += __shfl_down_sync(0xffffffffu, s, o);
    if ((t & 31) == 0) red[t >> 5] = s;
    __syncthreads();
    if (t == 0) {
        float band = 0.0f;
        #pragma unroll
        for (int w = 0; w < 8; ++w) band += red[w];
        g_level[b] = 10.0f * log10f(band * cnorm);
    }
}

__global__ void final_kernel(float* __restrict__ out)
{
    __shared__ float red[2];
    const int t = threadIdx.x;   // 64 threads
    float v = g_level[t];
    #pragma unroll
    for (int o = 16; o > 0; o >>= 1) v += __shfl_down_sync(0xffffffffu, v, o);
    if ((t & 31) == 0) red[t >> 5] = v;
    __syncthreads();
    if (t == 0) out[0] = (red[0] + red[1]) * (1.0f / (float)BATCH);
}

extern "C" void kernel_launch(void* const* d_in, const int* in_sizes, int n_in,
                              void* d_out, int out_size)
{
    const float* x = (const float*)d_in[0];
    float* out = (float*)d_out;

    double wp = 0.0;
    for (int i = 0; i < 512; ++i) {
        double w = 0.54 - 0.46 * cos(2.0 * M_PI * (double)i / 512.0);
        float wf = (float)w;
        wp += (double)wf * (double)wf;
    }
    float cnorm = (float)(1.0 / (wp * 3152.0 * (double)NSEG));

    init_tables<<<1, 512>>>();
    dim3 grid(NPAIR / 2, BATCH);
    fft_pair_kernel<<<grid, 128>>>(x);
    batch_reduce_kernel<<<BATCH, 256>>>(cnorm);
    final_kernel<<<1, 64>>>(out);
}

// round 3
// speedup vs baseline: 5.3468x; 1.3938x over previous
#include <cuda_runtime.h>
#include <math.h>

#define BATCH   64
#define T_LEN   262144
#define STEP    171
#define NSEG    1531
#define NPAIR   766
#define FS_F    3152.0f

// Scratch / tables (no allocations allowed)
__device__ float g_partial[BATCH * NPAIR];
__device__ float g_wp[512];   // folded one-sided A-weight per full-spectrum bin

__device__ __forceinline__ float aweight(int k) {
    // 10**(A(f)/10) = (num/den)^2 * 10^0.2   (A1000 = -2 folded in)
    float f   = k * (FS_F / 512.0f);
    float fsq = f * f;
    float num = (12194.0f * 12194.0f) * fsq * fsq;
    float den = (fsq + 20.6f * 20.6f)
              * sqrtf((fsq + 107.7f * 107.7f) * (fsq + 737.9f * 737.9f))
              * (fsq + 12194.0f * 12194.0f);
    float r = num / den;
    return r * r * 1.5848931924611136f;
}

__global__ void init_tables()
{
    int i = threadIdx.x;             // 512 threads
    int kp = (i < 256) ? i : (512 - i);
    g_wp[i] = (kp >= 1 && kp <= 243) ? aweight(kp) : 0.0f;
}

// In-place DFT-8 (natural order in/out): u_q = sum_p a_p * exp(-2pi i p q / 8)
__device__ __forceinline__ void dft8(float* xr, float* xi)
{
    const float C = 0.70710678118654752f;
    float e0r=xr[0]+xr[4], e0i=xi[0]+xi[4];
    float o0r=xr[0]-xr[4], o0i=xi[0]-xi[4];
    float e1r=xr[1]+xr[5], e1i=xi[1]+xi[5];
    float o1r=xr[1]-xr[5], o1i=xi[1]-xi[5];
    float e2r=xr[2]+xr[6], e2i=xi[2]+xi[6];
    float o2r=xr[2]-xr[6], o2i=xi[2]-xi[6];
    float e3r=xr[3]+xr[7], e3i=xi[3]+xi[7];
    float o3r=xr[3]-xr[7], o3i=xi[3]-xi[7];
    float t1r = C*(o1r + o1i), t1i = C*(o1i - o1r);
    float t2r = o2i,           t2i = -o2r;
    float t3r = C*(o3i - o3r), t3i = -C*(o3r + o3i);
    float a0r=e0r+e2r, a0i=e0i+e2i;
    float a1r=e0r-e2r, a1i=e0i-e2i;
    float a2r=e1r+e3r, a2i=e1i+e3i;
    float a3r=e1r-e3r, a3i=e1i-e3i;
    xr[0]=a0r+a2r; xi[0]=a0i+a2i;
    xr[4]=a0r-a2r; xi[4]=a0i-a2i;
    xr[2]=a1r+a3i; xi[2]=a1i-a3r;
    xr[6]=a1r-a3i; xi[6]=a1i+a3r;
    float b0r=o0r+t2r, b0i=o0i+t2i;
    float b1r=o0r-t2r, b1i=o0i-t2i;
    float b2r=t1r+t3r, b2i=t1i+t3i;
    float b3r=t1r-t3r, b3i=t1i-t3i;
    xr[1]=b0r+b2r; xi[1]=b0i+b2i;
    xr[5]=b0r-b2r; xi[5]=b0i-b2i;
    xr[3]=b1r+b3i; xi[3]=b1i-b3r;
    xr[7]=b1r-b3i; xi[7]=b1i+b3r;
}

// One 128-thread block = 2 packed-pair FFT-512s (64 threads each, 8 pts/thread).
__global__ __launch_bounds__(128) void fft_pair_kernel(const float* __restrict__ x)
{
    // Exchange buffer, reused for both exchanges. 576 floats per group/component.
    __shared__ float sxr[2][576], sxi[2][576];
    __shared__ float red[2][2];

    const int g = threadIdx.x >> 6;      // sub-group: which FFT
    const int t = threadIdx.x & 63;      // 0..63 within FFT
    const int j = blockIdx.x * 2 + g;    // pair index 0..765
    const int b = blockIdx.y;

    const float* xa = x + (size_t)b * T_LEN + (size_t)j * (2 * STEP);
    const bool has_b = (2 * j + 1) < NSEG;

    float vr[8], vi[8];

    // Window via one sincos + exact pi/4-step constants:
    // win[t+64p] = 0.54 - 0.46*cos(theta + p*pi/4), theta = 2*pi*t/512
    float st, ct;
    __sincosf((float)t * 0.012271846303085130f, &st, &ct);   // 2*pi/512
    const float R2 = 0.70710678118654752f;
    const float WC[8] = {1.0f,  R2, 0.0f, -R2, -1.0f, -R2,  0.0f,  R2};
    const float WS[8] = {0.0f,  R2, 1.0f,  R2,  0.0f, -R2, -1.0f, -R2};

    #pragma unroll
    for (int p = 0; p < 8; ++p) {
        int i = t + (p << 6);
        float w = 0.54f - 0.46f * (ct * WC[p] - st * WS[p]);
        vr[p] = xa[i] * w;
        vi[p] = has_b ? xa[i + STEP] * w : 0.0f;
    }

    // Pass 1: DFT-8 over p, twiddle W512^{t*q} generated by rotation chain.
    // Base W512^t = exp(-i*theta) = (ct, -st)  -- free from the window sincos.
    dft8(vr, vi);
    {
        const float c1 = ct, s1 = -st;
        float cw = c1, sw = s1;
        #pragma unroll
        for (int q = 1; q < 8; ++q) {
            float rr = vr[q], ii = vi[q];
            vr[q] = rr * cw - ii * sw;
            vi[q] = rr * sw + ii * cw;
            float nc = cw * c1 - sw * s1;
            sw = cw * s1 + sw * c1;
            cw = nc;
        }
    }

    // Exchange 1: addr = 72*q + t  (store); read addr = 72*qp + m + 8*s
    #pragma unroll
    for (int q = 0; q < 8; ++q) { sxr[g][72*q + t] = vr[q]; sxi[g][72*q + t] = vi[q]; }
    __syncthreads();
    const int qp = t >> 3, m = t & 7;
    #pragma unroll
    for (int s = 0; s < 8; ++s) {
        int a = 72 * qp + m + (s << 3);
        vr[s] = sxr[g][a];
        vi[s] = sxi[g][a];
    }
    __syncthreads();   // buffer reuse

    // Pass 2: DFT-8 over s, twiddle W64^{m*q2} via rotation chain.
    dft8(vr, vi);
    {
        float s2, c2;
        __sincosf((float)m * -0.098174770424681035f, &s2, &c2);  // -2*pi/64
        float cw = c2, sw = s2;
        #pragma unroll
        for (int q2 = 1; q2 < 8; ++q2) {
            float rr = vr[q2], ii = vi[q2];
            vr[q2] = rr * cw - ii * sw;
            vi[q2] = rr * sw + ii * cw;
            float nc = cw * c2 - sw * s2;
            sw = cw * s2 + sw * c2;
            cw = nc;
        }
    }

    // Exchange 2 (replaces shfl transpose): store addr = 8*qp + m + 33*q2,
    // read addr = 8*qp + r2 + 33*m. Conflict-free both directions.
    #pragma unroll
    for (int q2 = 0; q2 < 8; ++q2) {
        int a = (qp << 3) + m + 33 * q2;
        sxr[g][a] = vr[q2];
        sxi[g][a] = vi[q2];
    }
    __syncthreads();
    #pragma unroll
    for (int r2 = 0; r2 < 8; ++r2) {
        int a = (qp << 3) + r2 + 33 * m;
        vr[r2] = sxr[g][a];
        vi[r2] = sxi[g][a];
    }

    // Pass 3: DFT-8 over r2. Thread owns bins k = 64*r2 + 8*m + qp.
    dft8(vr, vi);

    const int base = (m << 3) + qp;
    float acc = 0.0f;
    #pragma unroll
    for (int r2 = 0; r2 < 8; ++r2) {
        int k = (r2 << 6) + base;
        acc += g_wp[k] * (vr[r2] * vr[r2] + vi[r2] * vi[r2]);
    }

    // Reduce 64 threads of this sub-group (deterministic tree)
    #pragma unroll
    for (int o = 16; o > 0; o >>= 1) acc += __shfl_down_sync(0xffffffffu, acc, o);
    if ((t & 31) == 0) red[g][t >> 5] = acc;
    __syncthreads();
    if (t == 0) g_partial[b * NPAIR + j] = red[g][0] + red[g][1];
}

// Single block: 16 threads per batch -> band sum -> 10*log10 -> mean over 64.
__global__ __launch_bounds__(1024) void reduce_all_kernel(float cnorm, float* __restrict__ out)
{
    __shared__ float lv[64];
    __shared__ float red[2];
    const int tid = threadIdx.x;
    const int b = tid >> 4;        // 0..63
    const int l = tid & 15;

    float s = 0.0f;
    for (int i = l; i < NPAIR; i += 16) s += g_partial[b * NPAIR + i];
    #pragma unroll
    for (int o = 8; o > 0; o >>= 1) s += __shfl_down_sync(0xffffffffu, s, o, 16);
    if (l == 0) lv[b] = 10.0f * log10f(s * cnorm);
    __syncthreads();

    if (tid < 64) {
        float v = lv[tid];
        #pragma unroll
        for (int o = 16; o > 0; o >>= 1) v += __shfl_down_sync(0xffffffffu, v, o);
        if ((tid & 31) == 0) red[tid >> 5] = v;
    }
    __syncthreads();
    if (tid == 0) out[0] = (red[0] + red[1]) * (1.0f / (float)BATCH);
}

extern "C" void kernel_launch(void* const* d_in, const int* in_sizes, int n_in,
                              void* d_out, int out_size)
{
    const float* x = (const float*)d_in[0];
    float* out = (float*)d_out;

    double wp = 0.0;
    for (int i = 0; i < 512; ++i) {
        double w = 0.54 - 0.46 * cos(2.0 * M_PI * (double)i / 512.0);
        float wf = (float)w;
        wp += (double)wf * (double)wf;
    }
    float cnorm = (float)(1.0 / (wp * 3152.0 * (double)NSEG));

    init_tables<<<1, 512>>>();
    dim3 grid(NPAIR / 2, BATCH);
    fft_pair_kernel<<<grid, 128>>>(x);
    reduce_all_kernel<<<1, 1024>>>(cnorm, out);
}